// round 14
// baseline (speedup 1.0000x reference)
#include <cuda_runtime.h>
#include <cstddef>
#include <cstdint>

// Problem constants (fixed by setup_inputs)
#define BATCH 1024
#define F1 10          // layer-1 fanout
#define F0 25          // layer-0 fanout
#define D 128          // feature dim
#define NROWS1 (BATCH*F1)        // 10240
#define NTOT (BATCH + NROWS1)    // 11264
#define RT 32                    // rows per layer-0 block (NTOT/RT = 352)

typedef unsigned long long u64;

// Scratch (device globals — no allocations allowed).
__device__ float  g_N[(size_t)NTOT * 256];
__device__ float2 g_W0i[128 * 128];   // (ws0, wn0) interleaved, [k][c]
__device__ float2 g_W1i[256 * 128];   // (ws1, wn1) interleaved, [k][c]

// f32x2 packed-FMA helpers (two independent rn-rounded fp32 FMAs per inst)
#define FMA2(d, a, b, c_) \
    asm("fma.rn.f32x2 %0, %1, %2, %3;" : "=l"(d) : "l"(a), "l"(b), "l"(c_))
#define UNPACK2(lo, hi, v) \
    asm("mov.b64 {%0, %1}, %2;" : "=f"(lo), "=f"(hi) : "l"(v))

// ---------------------------------------------------------------------------
// K0: build interleaved weight tables (deterministic, graph-capturable).
// ---------------------------------------------------------------------------
__global__ void k_prep(const float* __restrict__ ws0, const float* __restrict__ wn0,
                       const float* __restrict__ ws1, const float* __restrict__ wn1)
{
    int i = blockIdx.x * 256 + threadIdx.x;
    if (i < 16384) {
        g_W0i[i] = make_float2(ws0[i], wn0[i]);
    } else {
        int j = i - 16384;
        g_W1i[j] = make_float2(ws1[j], wn1[j]);
    }
}

// ---------------------------------------------------------------------------
// Gather: warp-cooperative. Warp w produces rows w, w+8, w+16, w+24, writing
// (self, nmean) INTERLEAVED per k. Neighbor loop unroll capped at 5: per-warp
// MLP 5 is enough chip-wide (4 blk/SM x 8 warps saturate LTS) and keeps the
// register count under the 64-reg cap that buys 4 blocks/SM.
// ---------------------------------------------------------------------------
template<int CNT, bool LVL0>
__device__ __forceinline__ void gather_rows(
    const float* __restrict__ features, const int* __restrict__ adj,
    const int* __restrict__ batch, int r0,
    float2 (*Xi)[D], int warp, int lane)
{
    #pragma unroll
    for (int rr = warp; rr < RT; rr += 8) {
        int r = r0 + rr;
        int s;
        if (LVL0) {
            s = __ldg(batch + r);
        } else {
            int i = r - BATCH;
            s = __ldg(adj + (size_t)__ldg(batch + i / F1) * 128 + (i % F1));
        }
        float4 sv = ((const float4*)(features + (size_t)s * D))[lane];

        const int* arow = adj + (size_t)s * 128;
        float4 acc = make_float4(0.f, 0.f, 0.f, 0.f);
        #pragma unroll 5
        for (int j = 0; j < CNT; j++) {
            int nb = __ldg(arow + j);
            float4 nv = ((const float4*)(features + (size_t)nb * D))[lane];
            acc.x += nv.x; acc.y += nv.y; acc.z += nv.z; acc.w += nv.w;
        }
        const float inv = 1.f / CNT;
        acc.x *= inv; acc.y *= inv; acc.z *= inv; acc.w *= inv;

        float4* dst = (float4*)&Xi[rr][4 * lane];
        dst[0] = make_float4(sv.x, acc.x, sv.y, acc.y);
        dst[1] = make_float4(sv.z, acc.z, sv.w, acc.w);
    }
}

// ---------------------------------------------------------------------------
// K_A: fused sample + aggregate + layer-0 GEMM (+ReLU), f32x2 packed.
// grid = 352 x 256 thr; block = 32 rows x 256 output cols.
// Thread owns paired columns (c, c+128) for 16 rows (tid>>7 selects row half).
// Register-dieted (<=64 regs, 4 blocks/SM) so gather of one block overlaps
// the GEMM of its SM-neighbors. Single-buffer weight groups (W0i is 128 KB ->
// L1-resident after first pass).
// ---------------------------------------------------------------------------
__global__ void __launch_bounds__(256, 4)
k_layer0(const float* __restrict__ features, const int* __restrict__ adj,
         const int* __restrict__ batch)
{
    __shared__ float2 Xi[RT][D];       // 32 KB interleaved (self, nmean)

    const int tid  = threadIdx.x;
    const int warp = tid >> 5, lane = tid & 31;
    const int r0   = blockIdx.x * RT;

    if (r0 < BATCH)
        gather_rows<F1, true >(features, adj, batch, r0, Xi, warp, lane);
    else
        gather_rows<F0, false>(features, adj, batch, r0, Xi, warp, lane);
    __syncthreads();

    const int c    = tid & 127;
    const int half = tid >> 7;          // 0: rows 0-15, 1: rows 16-31

    const u64* X = (const u64*)&Xi[half * 16][0];       // 16 rows x 128 k
    const u64* W = ((const u64*)g_W0i) + c;             // stride 128 per k

    u64 acc[16];
    #pragma unroll
    for (int r = 0; r < 16; r++) acc[r] = 0ull;

    #pragma unroll
    for (int g = 0; g < 16; g++) {
        u64 w2[8];
        #pragma unroll
        for (int j = 0; j < 8; j++)
            w2[j] = __ldg(W + (size_t)(g * 8 + j) * 128);
        #pragma unroll
        for (int j = 0; j < 8; j++) {
            const int k = g * 8 + j;
            #pragma unroll
            for (int r = 0; r < 16; r++) {
                u64 x = X[r * D + k];                  // broadcast LDS.64
                FMA2(acc[r], x, w2[j], acc[r]);
            }
        }
    }

    #pragma unroll
    for (int r = 0; r < 16; r++) {
        float lo, hi;
        UNPACK2(lo, hi, acc[r]);
        const size_t R = (size_t)(r0 + half * 16 + r);
        g_N[R * 256 + c]       = fmaxf(lo, 0.f);
        g_N[R * 256 + c + 128] = fmaxf(hi, 0.f);
    }
}

// ---------------------------------------------------------------------------
// K_B: fused tail: mean-of-10 + layer-1 GEMM (f32x2) + l2-normalize + pred.
// (unchanged from round 13)
// ---------------------------------------------------------------------------
__global__ void __launch_bounds__(256)
k_tail(const float* __restrict__ wp, float* __restrict__ out)
{
    __shared__ float2 Ni[8][256];      // 16 KB interleaved (n0, m1)
    __shared__ float  inv8[8];

    const int tid  = threadIdx.x;
    const int warp = tid >> 5, lane = tid & 31;
    const int r0   = blockIdx.x * 8;

    // Phase 1: one row per warp. lane covers k = 8*lane .. 8*lane+7.
    {
        const int R = r0 + warp;
        const float4* n0p = (const float4*)(g_N + (size_t)R * 256);
        float4 a0 = n0p[2 * lane], a1 = n0p[2 * lane + 1];

        const float* mb = g_N + (size_t)(BATCH + R * F1) * 256;
        float4 b0 = make_float4(0.f, 0.f, 0.f, 0.f);
        float4 b1 = make_float4(0.f, 0.f, 0.f, 0.f);
        #pragma unroll
        for (int j = 0; j < F1; j++) {
            const float4* mp = (const float4*)(mb + (size_t)j * 256);
            float4 t0 = mp[2 * lane], t1 = mp[2 * lane + 1];
            b0.x += t0.x; b0.y += t0.y; b0.z += t0.z; b0.w += t0.w;
            b1.x += t1.x; b1.y += t1.y; b1.z += t1.z; b1.w += t1.w;
        }
        const float inv = 1.f / F1;
        b0.x *= inv; b0.y *= inv; b0.z *= inv; b0.w *= inv;
        b1.x *= inv; b1.y *= inv; b1.z *= inv; b1.w *= inv;

        float4* dst = (float4*)&Ni[warp][8 * lane];
        dst[0] = make_float4(a0.x, b0.x, a0.y, b0.y);
        dst[1] = make_float4(a0.z, b0.z, a0.w, b0.w);
        dst[2] = make_float4(a1.x, b1.x, a1.y, b1.y);
        dst[3] = make_float4(a1.z, b1.z, a1.w, b1.w);
    }
    __syncthreads();

    // Phase 2: GEMM K=256. Thread owns paired cols (c, c+128) for 4 rows.
    const int c    = tid & 127;
    const int half = tid >> 7;          // rows 0-3 or 4-7

    const u64* X = (const u64*)&Ni[half * 4][0];
    const u64* W = ((const u64*)g_W1i) + c;

    u64 acc[4] = {0ull, 0ull, 0ull, 0ull};
    u64 w2[2][8];
    #pragma unroll
    for (int j = 0; j < 8; j++)
        w2[0][j] = __ldg(W + (size_t)j * 128);

    #pragma unroll
    for (int g = 0; g < 32; g++) {
        const int cur = g & 1, nxt = cur ^ 1;
        if (g < 31) {
            #pragma unroll
            for (int j = 0; j < 8; j++)
                w2[nxt][j] = __ldg(W + (size_t)((g + 1) * 8 + j) * 128);
        }
        #pragma unroll
        for (int j = 0; j < 8; j++) {
            const int k = g * 8 + j;
            #pragma unroll
            for (int r = 0; r < 4; r++) {
                u64 x = X[r * 256 + k];
                FMA2(acc[r], x, w2[cur][j], acc[r]);
            }
        }
    }
    __syncthreads();                    // all Ni reads done -> safe to alias

    float* Ys = (float*)Ni;             // [8][256]
    #pragma unroll
    for (int r = 0; r < 4; r++) {
        float lo, hi;
        UNPACK2(lo, hi, acc[r]);
        const int rr = half * 4 + r;
        Ys[rr * 256 + c]       = lo;
        Ys[rr * 256 + c + 128] = hi;
    }
    __syncthreads();

    // Phase 3: per-row inverse L2 norm (warp w reduces row w)
    {
        float s = 0.f;
        #pragma unroll
        for (int k = lane; k < 256; k += 32) {
            float v = Ys[warp * 256 + k];
            s += v * v;
        }
        #pragma unroll
        for (int o = 16; o > 0; o >>= 1)
            s += __shfl_xor_sync(0xFFFFFFFFu, s, o);
        if (lane == 0)
            inv8[warp] = rsqrtf(fmaxf(s, 1e-12f));
    }
    __syncthreads();

    // Phase 4: pred head [256 -> 50]; normalization folded as output scale.
    const int cc = tid & 63;
    const int rg = tid >> 6;            // 4 groups x 2 rows
    if (cc < 50) {
        const int rl = rg * 2;
        float a0 = 0.f, a1 = 0.f;
        #pragma unroll 16
        for (int k = 0; k < 256; k++) {
            float w = __ldg(wp + (size_t)k * 50 + cc);
            a0 = fmaf(Ys[rl * 256 + k], w, a0);
            a1 = fmaf(Ys[(rl + 1) * 256 + k], w, a1);
        }
        out[(size_t)(r0 + rl) * 50 + cc]     = a0 * inv8[rl];
        out[(size_t)(r0 + rl + 1) * 50 + cc] = a1 * inv8[rl + 1];
    }
}

// ---------------------------------------------------------------------------
extern "C" void kernel_launch(void* const* d_in, const int* in_sizes, int n_in,
                              void* d_out, int out_size)
{
    const float* features = (const float*)d_in[0];
    const int*   adj      = (const int*)d_in[1];
    const int*   batch    = (const int*)d_in[2];   // int32 (JAX x64 disabled)
    const float* ws0      = (const float*)d_in[3];
    const float* wn0      = (const float*)d_in[4];
    const float* ws1      = (const float*)d_in[5];
    const float* wn1      = (const float*)d_in[6];
    const float* wp       = (const float*)d_in[7];
    float*       out      = (float*)d_out;

    k_prep<<<192, 256>>>(ws0, wn0, ws1, wn1);
    k_layer0<<<NTOT / RT, 256>>>(features, adj, batch);
    k_tail<<<BATCH / 8, 256>>>(wp, out);
}

// round 16
// speedup vs baseline: 1.0334x; 1.0334x over previous
#include <cuda_runtime.h>
#include <cstddef>
#include <cstdint>

// Problem constants (fixed by setup_inputs)
#define BATCH 1024
#define F1 10          // layer-1 fanout
#define F0 25          // layer-0 fanout
#define D 128          // feature dim
#define NROWS1 (BATCH*F1)        // 10240
#define NTOT (BATCH + NROWS1)    // 11264
#define RT 32                    // rows per layer-0 GEMM block (NTOT/RT = 352)

typedef unsigned long long u64;

// Scratch (device globals — no allocations allowed).
__device__ float  g_N[(size_t)NTOT * 256];
__device__ float2 g_Xi[(size_t)NTOT * D];   // interleaved (self, nmean), 11.5 MB

// f32x2 packed-FMA helpers (two independent rn-rounded fp32 FMAs per inst)
#define FMA2(d, a, b, c_) \
    asm("fma.rn.f32x2 %0, %1, %2, %3;" : "=l"(d) : "l"(a), "l"(b), "l"(c_))
#define UNPACK2(lo, hi, v) \
    asm("mov.b64 {%0, %1}, %2;" : "=f"(lo), "=f"(hi) : "l"(v))
#define PACK2(d, lo, hi) \
    asm("mov.b64 %0, {%1, %2};" : "=l"(d) : "f"(lo), "f"(hi))

// ---------------------------------------------------------------------------
// K_G: sample + aggregate only. One row per warp; grid = NTOT/8 = 1408 blocks.
// Pure memory kernel: small reg footprint + fully unrolled neighbor loop ->
// max occupancy and max MLP. Writes interleaved (self, nmean) to g_Xi.
// ---------------------------------------------------------------------------
template<int CNT, bool LVL0>
__device__ __forceinline__ void gather_row(
    const float* __restrict__ features, const int* __restrict__ adj,
    const int* __restrict__ batch, int r, int lane)
{
    int s;
    if (LVL0) {
        s = __ldg(batch + r);
    } else {
        int i = r - BATCH;
        s = __ldg(adj + (size_t)__ldg(batch + i / F1) * 128 + (i % F1));
    }
    float4 sv = ((const float4*)(features + (size_t)s * D))[lane];

    const int* arow = adj + (size_t)s * 128;
    float4 acc = make_float4(0.f, 0.f, 0.f, 0.f);
    #pragma unroll
    for (int j = 0; j < CNT; j++) {
        int nb = __ldg(arow + j);
        float4 nv = ((const float4*)(features + (size_t)nb * D))[lane];
        acc.x += nv.x; acc.y += nv.y; acc.z += nv.z; acc.w += nv.w;
    }
    const float inv = 1.f / CNT;
    acc.x *= inv; acc.y *= inv; acc.z *= inv; acc.w *= inv;

    float4* dst = (float4*)&g_Xi[(size_t)r * D + 4 * lane];
    dst[0] = make_float4(sv.x, acc.x, sv.y, acc.y);
    dst[1] = make_float4(sv.z, acc.z, sv.w, acc.w);
}

__global__ void __launch_bounds__(256)
k_gather(const float* __restrict__ features, const int* __restrict__ adj,
         const int* __restrict__ batch)
{
    const int warp = threadIdx.x >> 5, lane = threadIdx.x & 31;
    const int r = blockIdx.x * 8 + warp;
    if (r < BATCH)
        gather_row<F1, true >(features, adj, batch, r, lane);
    else
        gather_row<F0, false>(features, adj, batch, r, lane);
}

// ---------------------------------------------------------------------------
// K_A: layer-0 GEMM (+ReLU), f32x2 packed. grid = 352 x 256 thr.
// Tile = 32 rows x 128 float2 = 32 KB = 2048 float4 -> 8 float4 per thread
// (round-15 bug: copied 4x too much -> smem/global OOB). Thread owns paired
// columns (c, c+128) for 16 rows. Weights packed in-register. NO reg cap.
// ---------------------------------------------------------------------------
__global__ void __launch_bounds__(256)
k_gemm0(const float* __restrict__ ws0, const float* __restrict__ wn0)
{
    __shared__ float2 Xi[RT][D];       // 32 KB interleaved (self, nmean)

    const int tid = threadIdx.x;
    const int r0  = blockIdx.x * RT;

    // Coalesced tile load: 2048 float4 across 256 threads = 8 each.
    {
        const float4* src = (const float4*)&g_Xi[(size_t)r0 * D];
        float4* dst = (float4*)&Xi[0][0];
        #pragma unroll
        for (int i = 0; i < 8; i++)
            dst[i * 256 + tid] = src[i * 256 + tid];
    }
    __syncthreads();

    const int c    = tid & 127;
    const int half = tid >> 7;          // 0: rows 0-15, 1: rows 16-31

    const u64* X = (const u64*)&Xi[half * 16][0];       // 16 rows x 128 k
    const float* Ws = ws0 + c;
    const float* Wn = wn0 + c;

    u64 acc[16];
    #pragma unroll
    for (int r = 0; r < 16; r++) acc[r] = 0ull;

    #pragma unroll
    for (int g = 0; g < 16; g++) {
        u64 w2[8];
        #pragma unroll
        for (int j = 0; j < 8; j++) {
            float lo = __ldg(Ws + (size_t)(g * 8 + j) * 128);
            float hi = __ldg(Wn + (size_t)(g * 8 + j) * 128);
            PACK2(w2[j], lo, hi);
        }
        #pragma unroll
        for (int j = 0; j < 8; j++) {
            const int k = g * 8 + j;
            #pragma unroll
            for (int r = 0; r < 16; r++) {
                u64 x = X[r * D + k];                  // broadcast LDS.64
                FMA2(acc[r], x, w2[j], acc[r]);
            }
        }
    }

    #pragma unroll
    for (int r = 0; r < 16; r++) {
        float lo, hi;
        UNPACK2(lo, hi, acc[r]);
        const size_t R = (size_t)(r0 + half * 16 + r);
        g_N[R * 256 + c]       = fmaxf(lo, 0.f);
        g_N[R * 256 + c + 128] = fmaxf(hi, 0.f);
    }
}

// ---------------------------------------------------------------------------
// K_B: fused tail: mean-of-10 + layer-1 GEMM (f32x2) + l2-normalize + pred.
// Weights packed in-register (no prep kernel).
// ---------------------------------------------------------------------------
__global__ void __launch_bounds__(256)
k_tail(const float* __restrict__ ws1, const float* __restrict__ wn1,
       const float* __restrict__ wp, float* __restrict__ out)
{
    __shared__ float2 Ni[8][256];      // 16 KB interleaved (n0, m1)
    __shared__ float  inv8[8];

    const int tid  = threadIdx.x;
    const int warp = tid >> 5, lane = tid & 31;
    const int r0   = blockIdx.x * 8;

    // Phase 1: one row per warp. lane covers k = 8*lane .. 8*lane+7.
    {
        const int R = r0 + warp;
        const float4* n0p = (const float4*)(g_N + (size_t)R * 256);
        float4 a0 = n0p[2 * lane], a1 = n0p[2 * lane + 1];

        const float* mb = g_N + (size_t)(BATCH + R * F1) * 256;
        float4 b0 = make_float4(0.f, 0.f, 0.f, 0.f);
        float4 b1 = make_float4(0.f, 0.f, 0.f, 0.f);
        #pragma unroll
        for (int j = 0; j < F1; j++) {
            const float4* mp = (const float4*)(mb + (size_t)j * 256);
            float4 t0 = mp[2 * lane], t1 = mp[2 * lane + 1];
            b0.x += t0.x; b0.y += t0.y; b0.z += t0.z; b0.w += t0.w;
            b1.x += t1.x; b1.y += t1.y; b1.z += t1.z; b1.w += t1.w;
        }
        const float inv = 1.f / F1;
        b0.x *= inv; b0.y *= inv; b0.z *= inv; b0.w *= inv;
        b1.x *= inv; b1.y *= inv; b1.z *= inv; b1.w *= inv;

        float4* dst = (float4*)&Ni[warp][8 * lane];
        dst[0] = make_float4(a0.x, b0.x, a0.y, b0.y);
        dst[1] = make_float4(a0.z, b0.z, a0.w, b0.w);
        dst[2] = make_float4(a1.x, b1.x, a1.y, b1.y);
        dst[3] = make_float4(a1.z, b1.z, a1.w, b1.w);
    }
    __syncthreads();

    // Phase 2: GEMM K=256. Thread owns paired cols (c, c+128) for 4 rows.
    const int c    = tid & 127;
    const int half = tid >> 7;          // rows 0-3 or 4-7

    const u64* X = (const u64*)&Ni[half * 4][0];
    const float* Ws = ws1 + c;
    const float* Wn = wn1 + c;

    u64 acc[4] = {0ull, 0ull, 0ull, 0ull};

    #pragma unroll
    for (int g = 0; g < 32; g++) {
        u64 w2[8];
        #pragma unroll
        for (int j = 0; j < 8; j++) {
            float lo = __ldg(Ws + (size_t)(g * 8 + j) * 128);
            float hi = __ldg(Wn + (size_t)(g * 8 + j) * 128);
            PACK2(w2[j], lo, hi);
        }
        #pragma unroll
        for (int j = 0; j < 8; j++) {
            const int k = g * 8 + j;
            #pragma unroll
            for (int r = 0; r < 4; r++) {
                u64 x = X[r * 256 + k];
                FMA2(acc[r], x, w2[j], acc[r]);
            }
        }
    }
    __syncthreads();                    // all Ni reads done -> safe to alias

    float* Ys = (float*)Ni;             // [8][256]
    #pragma unroll
    for (int r = 0; r < 4; r++) {
        float lo, hi;
        UNPACK2(lo, hi, acc[r]);
        const int rr = half * 4 + r;
        Ys[rr * 256 + c]       = lo;
        Ys[rr * 256 + c + 128] = hi;
    }
    __syncthreads();

    // Phase 3: per-row inverse L2 norm (warp w reduces row w)
    {
        float s = 0.f;
        #pragma unroll
        for (int k = lane; k < 256; k += 32) {
            float v = Ys[warp * 256 + k];
            s += v * v;
        }
        #pragma unroll
        for (int o = 16; o > 0; o >>= 1)
            s += __shfl_xor_sync(0xFFFFFFFFu, s, o);
        if (lane == 0)
            inv8[warp] = rsqrtf(fmaxf(s, 1e-12f));
    }
    __syncthreads();

    // Phase 4: pred head [256 -> 50]; normalization folded as output scale.
    const int cc = tid & 63;
    const int rg = tid >> 6;            // 4 groups x 2 rows
    if (cc < 50) {
        const int rl = rg * 2;
        float a0 = 0.f, a1 = 0.f;
        #pragma unroll 16
        for (int k = 0; k < 256; k++) {
            float w = __ldg(wp + (size_t)k * 50 + cc);
            a0 = fmaf(Ys[rl * 256 + k], w, a0);
            a1 = fmaf(Ys[(rl + 1) * 256 + k], w, a1);
        }
        out[(size_t)(r0 + rl) * 50 + cc]     = a0 * inv8[rl];
        out[(size_t)(r0 + rl + 1) * 50 + cc] = a1 * inv8[rl + 1];
    }
}

// ---------------------------------------------------------------------------
extern "C" void kernel_launch(void* const* d_in, const int* in_sizes, int n_in,
                              void* d_out, int out_size)
{
    const float* features = (const float*)d_in[0];
    const int*   adj      = (const int*)d_in[1];
    const int*   batch    = (const int*)d_in[2];   // int32 (JAX x64 disabled)
    const float* ws0      = (const float*)d_in[3];
    const float* wn0      = (const float*)d_in[4];
    const float* ws1      = (const float*)d_in[5];
    const float* wn1      = (const float*)d_in[6];
    const float* wp       = (const float*)d_in[7];
    float*       out      = (float*)d_out;

    k_gather<<<NTOT / 8, 256>>>(features, adj, batch);
    k_gemm0<<<NTOT / RT, 256>>>(ws0, wn0);
    k_tail<<<BATCH / 8, 256>>>(ws1, wn1, wp, out);
}

// round 17
// speedup vs baseline: 1.3350x; 1.2918x over previous
#include <cuda_runtime.h>
#include <cstddef>
#include <cstdint>

// Problem constants (fixed by setup_inputs)
#define BATCH 1024
#define F1 10          // layer-1 fanout
#define F0 25          // layer-0 fanout
#define D 128          // feature dim
#define NROWS1 (BATCH*F1)        // 10240
#define NTOT (BATCH + NROWS1)    // 11264
#define RT 32                    // rows per layer-0 GEMM block (NTOT/RT = 352)

typedef unsigned long long u64;

// Scratch (device globals — no allocations allowed).
__device__ float  g_N[(size_t)NTOT * 256];
__device__ float2 g_Xi[(size_t)NTOT * D];   // interleaved (self, nmean), 11.5 MB
__device__ float2 g_W0i[128 * 128];         // (ws0, wn0) interleaved, [k][c]
__device__ float2 g_W1i[256 * 128];         // (ws1, wn1) interleaved, [k][c]

// f32x2 packed-FMA helpers (two independent rn-rounded fp32 FMAs per inst)
#define FMA2(d, a, b, c_) \
    asm("fma.rn.f32x2 %0, %1, %2, %3;" : "=l"(d) : "l"(a), "l"(b), "l"(c_))
#define UNPACK2(lo, hi, v) \
    asm("mov.b64 {%0, %1}, %2;" : "=f"(lo), "=f"(hi) : "l"(v))

// ---------------------------------------------------------------------------
// K_G: sample + aggregate (one row per warp, grid = 1408) + weight-table prep
// folded into blocks [0,192): thread i copies one float2 into W0i/W1i.
// Kernel boundary guarantees tables are complete before the GEMMs read them.
// ---------------------------------------------------------------------------
template<int CNT, bool LVL0>
__device__ __forceinline__ void gather_row(
    const float* __restrict__ features, const int* __restrict__ adj,
    const int* __restrict__ batch, int r, int lane)
{
    int s;
    if (LVL0) {
        s = __ldg(batch + r);
    } else {
        int i = r - BATCH;
        s = __ldg(adj + (size_t)__ldg(batch + i / F1) * 128 + (i % F1));
    }
    float4 sv = ((const float4*)(features + (size_t)s * D))[lane];

    const int* arow = adj + (size_t)s * 128;
    float4 acc = make_float4(0.f, 0.f, 0.f, 0.f);
    #pragma unroll
    for (int j = 0; j < CNT; j++) {
        int nb = __ldg(arow + j);
        float4 nv = ((const float4*)(features + (size_t)nb * D))[lane];
        acc.x += nv.x; acc.y += nv.y; acc.z += nv.z; acc.w += nv.w;
    }
    const float inv = 1.f / CNT;
    acc.x *= inv; acc.y *= inv; acc.z *= inv; acc.w *= inv;

    float4* dst = (float4*)&g_Xi[(size_t)r * D + 4 * lane];
    dst[0] = make_float4(sv.x, acc.x, sv.y, acc.y);
    dst[1] = make_float4(sv.z, acc.z, sv.w, acc.w);
}

__global__ void __launch_bounds__(256)
k_gather(const float* __restrict__ features, const int* __restrict__ adj,
         const int* __restrict__ batch,
         const float* __restrict__ ws0, const float* __restrict__ wn0,
         const float* __restrict__ ws1, const float* __restrict__ wn1)
{
    // Folded weight prep: 49152 float2 across blocks [0,192)
    if (blockIdx.x < 192) {
        int i = blockIdx.x * 256 + threadIdx.x;
        if (i < 16384)
            g_W0i[i] = make_float2(__ldg(ws0 + i), __ldg(wn0 + i));
        else {
            int j = i - 16384;
            g_W1i[j] = make_float2(__ldg(ws1 + j), __ldg(wn1 + j));
        }
    }

    const int warp = threadIdx.x >> 5, lane = threadIdx.x & 31;
    const int r = blockIdx.x * 8 + warp;
    if (r < BATCH)
        gather_row<F1, true >(features, adj, batch, r, lane);
    else
        gather_row<F0, false>(features, adj, batch, r, lane);
}

// ---------------------------------------------------------------------------
// K_A: layer-0 GEMM (+ReLU), f32x2 packed, round-13 loop (LDG.64 interleaved
// weights, register double-buffer). grid = 352 x 256 thr; tile = 32 rows x
// 128 float2 = 2048 float4 -> 8 per thread. NO register cap.
// ---------------------------------------------------------------------------
__global__ void __launch_bounds__(256)
k_gemm0()
{
    __shared__ float2 Xi[RT][D];       // 32 KB interleaved (self, nmean)

    const int tid = threadIdx.x;
    const int r0  = blockIdx.x * RT;

    {
        const float4* src = (const float4*)&g_Xi[(size_t)r0 * D];
        float4* dst = (float4*)&Xi[0][0];
        #pragma unroll
        for (int i = 0; i < 8; i++)
            dst[i * 256 + tid] = src[i * 256 + tid];
    }
    __syncthreads();

    const int c    = tid & 127;
    const int half = tid >> 7;          // 0: rows 0-15, 1: rows 16-31

    const u64* X = (const u64*)&Xi[half * 16][0];       // 16 rows x 128 k
    const u64* W = ((const u64*)g_W0i) + c;             // stride 128 per k

    u64 acc[16];
    #pragma unroll
    for (int r = 0; r < 16; r++) acc[r] = 0ull;

    u64 w2[2][8];
    #pragma unroll
    for (int j = 0; j < 8; j++)
        w2[0][j] = __ldg(W + (size_t)j * 128);

    #pragma unroll
    for (int g = 0; g < 16; g++) {
        const int cur = g & 1, nxt = cur ^ 1;
        if (g < 15) {
            #pragma unroll
            for (int j = 0; j < 8; j++)
                w2[nxt][j] = __ldg(W + (size_t)((g + 1) * 8 + j) * 128);
        }
        #pragma unroll
        for (int j = 0; j < 8; j++) {
            const int k = g * 8 + j;
            #pragma unroll
            for (int r = 0; r < 16; r++) {
                u64 x = X[r * D + k];                  // broadcast LDS.64
                FMA2(acc[r], x, w2[cur][j], acc[r]);
            }
        }
    }

    #pragma unroll
    for (int r = 0; r < 16; r++) {
        float lo, hi;
        UNPACK2(lo, hi, acc[r]);
        const size_t R = (size_t)(r0 + half * 16 + r);
        g_N[R * 256 + c]       = fmaxf(lo, 0.f);
        g_N[R * 256 + c + 128] = fmaxf(hi, 0.f);
    }
}

// ---------------------------------------------------------------------------
// K_B: fused tail: mean-of-10 + layer-1 GEMM (f32x2) + l2-normalize + pred.
// Round-13 version exactly (g_W1i interleaved weights, double-buffered).
// ---------------------------------------------------------------------------
__global__ void __launch_bounds__(256)
k_tail(const float* __restrict__ wp, float* __restrict__ out)
{
    __shared__ float2 Ni[8][256];      // 16 KB interleaved (n0, m1)
    __shared__ float  inv8[8];

    const int tid  = threadIdx.x;
    const int warp = tid >> 5, lane = tid & 31;
    const int r0   = blockIdx.x * 8;

    // Phase 1: one row per warp. lane covers k = 8*lane .. 8*lane+7.
    {
        const int R = r0 + warp;
        const float4* n0p = (const float4*)(g_N + (size_t)R * 256);
        float4 a0 = n0p[2 * lane], a1 = n0p[2 * lane + 1];

        const float* mb = g_N + (size_t)(BATCH + R * F1) * 256;
        float4 b0 = make_float4(0.f, 0.f, 0.f, 0.f);
        float4 b1 = make_float4(0.f, 0.f, 0.f, 0.f);
        #pragma unroll
        for (int j = 0; j < F1; j++) {
            const float4* mp = (const float4*)(mb + (size_t)j * 256);
            float4 t0 = mp[2 * lane], t1 = mp[2 * lane + 1];
            b0.x += t0.x; b0.y += t0.y; b0.z += t0.z; b0.w += t0.w;
            b1.x += t1.x; b1.y += t1.y; b1.z += t1.z; b1.w += t1.w;
        }
        const float inv = 1.f / F1;
        b0.x *= inv; b0.y *= inv; b0.z *= inv; b0.w *= inv;
        b1.x *= inv; b1.y *= inv; b1.z *= inv; b1.w *= inv;

        float4* dst = (float4*)&Ni[warp][8 * lane];
        dst[0] = make_float4(a0.x, b0.x, a0.y, b0.y);
        dst[1] = make_float4(a0.z, b0.z, a0.w, b0.w);
        dst[2] = make_float4(a1.x, b1.x, a1.y, b1.y);
        dst[3] = make_float4(a1.z, b1.z, a1.w, b1.w);
    }
    __syncthreads();

    // Phase 2: GEMM K=256. Thread owns paired cols (c, c+128) for 4 rows.
    const int c    = tid & 127;
    const int half = tid >> 7;          // rows 0-3 or 4-7

    const u64* X = (const u64*)&Ni[half * 4][0];
    const u64* W = ((const u64*)g_W1i) + c;

    u64 acc[4] = {0ull, 0ull, 0ull, 0ull};
    u64 w2[2][8];
    #pragma unroll
    for (int j = 0; j < 8; j++)
        w2[0][j] = __ldg(W + (size_t)j * 128);

    #pragma unroll
    for (int g = 0; g < 32; g++) {
        const int cur = g & 1, nxt = cur ^ 1;
        if (g < 31) {
            #pragma unroll
            for (int j = 0; j < 8; j++)
                w2[nxt][j] = __ldg(W + (size_t)((g + 1) * 8 + j) * 128);
        }
        #pragma unroll
        for (int j = 0; j < 8; j++) {
            const int k = g * 8 + j;
            #pragma unroll
            for (int r = 0; r < 4; r++) {
                u64 x = X[r * 256 + k];
                FMA2(acc[r], x, w2[cur][j], acc[r]);
            }
        }
    }
    __syncthreads();                    // all Ni reads done -> safe to alias

    float* Ys = (float*)Ni;             // [8][256]
    #pragma unroll
    for (int r = 0; r < 4; r++) {
        float lo, hi;
        UNPACK2(lo, hi, acc[r]);
        const int rr = half * 4 + r;
        Ys[rr * 256 + c]       = lo;
        Ys[rr * 256 + c + 128] = hi;
    }
    __syncthreads();

    // Phase 3: per-row inverse L2 norm (warp w reduces row w)
    {
        float s = 0.f;
        #pragma unroll
        for (int k = lane; k < 256; k += 32) {
            float v = Ys[warp * 256 + k];
            s += v * v;
        }
        #pragma unroll
        for (int o = 16; o > 0; o >>= 1)
            s += __shfl_xor_sync(0xFFFFFFFFu, s, o);
        if (lane == 0)
            inv8[warp] = rsqrtf(fmaxf(s, 1e-12f));
    }
    __syncthreads();

    // Phase 4: pred head [256 -> 50]; normalization folded as output scale.
    const int cc = tid & 63;
    const int rg = tid >> 6;            // 4 groups x 2 rows
    if (cc < 50) {
        const int rl = rg * 2;
        float a0 = 0.f, a1 = 0.f;
        #pragma unroll 16
        for (int k = 0; k < 256; k++) {
            float w = __ldg(wp + (size_t)k * 50 + cc);
            a0 = fmaf(Ys[rl * 256 + k], w, a0);
            a1 = fmaf(Ys[(rl + 1) * 256 + k], w, a1);
        }
        out[(size_t)(r0 + rl) * 50 + cc]     = a0 * inv8[rl];
        out[(size_t)(r0 + rl + 1) * 50 + cc] = a1 * inv8[rl + 1];
    }
}

// ---------------------------------------------------------------------------
extern "C" void kernel_launch(void* const* d_in, const int* in_sizes, int n_in,
                              void* d_out, int out_size)
{
    const float* features = (const float*)d_in[0];
    const int*   adj      = (const int*)d_in[1];
    const int*   batch    = (const int*)d_in[2];   // int32 (JAX x64 disabled)
    const float* ws0      = (const float*)d_in[3];
    const float* wn0      = (const float*)d_in[4];
    const float* ws1      = (const float*)d_in[5];
    const float* wn1      = (const float*)d_in[6];
    const float* wp       = (const float*)d_in[7];
    float*       out      = (float*)d_out;

    k_gather<<<NTOT / 8, 256>>>(features, adj, batch, ws0, wn0, ws1, wn1);
    k_gemm0<<<NTOT / RT, 256>>>();
    k_tail<<<BATCH / 8, 256>>>(wp, out);
}